// round 12
// baseline (speedup 1.0000x reference)
#include <cuda_runtime.h>
#include <cuda_bf16.h>
#include <cstdint>

// Problem constants
#define BATCH 32
#define N_ROI 2000
#define N_GT  100
#define N_LAB 21
#define K_POS 64
#define ROWS_PER_B (N_ROI * N_LAB)            // 42000
#define DELTA_FLOATS (BATCH * ROWS_PER_B * 4) // 5,376,000
#define TOTAL_ROWS (BATCH * ROWS_PER_B)       // 1,344,000 (delta float4s; also label floats)
#define LAB_VEC4 (TOTAL_ROWS / 4)             // 336,000 label float4s
#define ALL_VEC4 (TOTAL_ROWS + LAB_VEC4)      // 1,680,000 fused float4 stores
#define RPB 64                                 // rois per iou block
#define IBLK 1024                              // 32 chunks x 32 batches (= grid size)
#define WVEC 1024                              // float4s per writer tile
#define WTILES ((ALL_VEC4 + WVEC - 1) / WVEC)  // 1641 writer tiles

// Scratch (device globals; zero-initialized at module load; no runtime alloc)
__device__ unsigned int g_merged[BATCH * N_ROI];
__device__ int          g_maxidx[BATCH * N_ROI];
__device__ int          g_label [BATCH * N_ROI];   // gt label if positive, else -1
__device__ float4       g_delta [BATCH * N_ROI];   // valid only when positive
__device__ int          g_count [BATCH];           // iou blocks done per batch
__device__ int          g_flag  [BATCH];           // select done per batch
__device__ int          g_wdone;                   // blocks fully done

__device__ __forceinline__ void waitb(int b)
{
    while (true) {
        int f;
        asm volatile("ld.acquire.gpu.b32 %0, [%1];"
                     : "=r"(f) : "l"(&g_flag[b]) : "memory");
        if (f) break;
        __nanosleep(64);
    }
}

// ---------------------------------------------------------------------------
// Select (256 threads, runs in the last-arriving iou block of a batch):
// exact stable-sort top-64 semantics via 4-pass radix select + index-ordered
// tie prefix, then per-roi label/delta records. Thread t owns rois [8t, 8t+8).
// ---------------------------------------------------------------------------
__device__ void do_select(int b, const float4* __restrict__ roi,
                          const float4* __restrict__ gt,
                          const int* __restrict__ gtlab, int t)
{
    __shared__ unsigned int hist[256];
    __shared__ unsigned int ssum[256];
    __shared__ unsigned int s_prefix, s_k;
    __shared__ int warp_sums[8];

    const int lane = t & 31, wrp = t >> 5;
    const bool act = (t < 250);                  // 250 * 8 = 2000
    const unsigned int* gm = g_merged + b * N_ROI;

    unsigned v[8];
#pragma unroll
    for (int i = 0; i < 8; ++i) v[i] = act ? gm[t * 8 + i] : 0u;
    if (t == 0) { s_prefix = 0u; s_k = K_POS; }
    __syncthreads();

#pragma unroll
    for (int pass = 0; pass < 4; ++pass) {
        const int shift = 24 - 8 * pass;
        hist[t] = 0u;
        __syncthreads();
        const unsigned pfx = s_prefix;
        const unsigned kk0 = s_k;
        const unsigned hm = (pass == 0) ? 0u
                          : (0xFFFFFFFFu << ((shift + 8 > 31) ? 31 : shift + 8));
#pragma unroll
        for (int i = 0; i < 8; ++i) {
            unsigned key = 0x100u, bin = 0u;
            if (act && (v[i] & hm) == (pfx & hm)) { bin = (v[i] >> shift) & 255u; key = bin; }
            const unsigned mmask = __match_any_sync(0xFFFFFFFFu, key);
            if (key != 0x100u && lane == (__ffs(mmask) - 1))
                atomicAdd(&hist[bin], (unsigned)__popc(mmask));
        }
        __syncthreads();
        if (t < 32) {       // single-warp suffix sum over 256 bins
            unsigned w[8], sum = 0u;
#pragma unroll
            for (int i = 0; i < 8; ++i) { w[i] = hist[t * 8 + i]; sum += w[i]; }
            unsigned suf = sum;
#pragma unroll
            for (int off = 1; off < 32; off <<= 1) {
                const unsigned x = __shfl_down_sync(0xFFFFFFFFu, suf, off);
                if (t + off < 32) suf += x;
            }
            unsigned acc = suf - sum;
#pragma unroll
            for (int i = 7; i >= 0; --i) { acc += w[i]; ssum[t * 8 + i] = acc; }
        }
        __syncthreads();
        {
            const unsigned cum   = ssum[t];
            const unsigned above = (t < 255) ? ssum[t + 1] : 0u;
            if (cum >= kk0 && above < kk0) {
                s_prefix = pfx | ((unsigned)t << shift);
                s_k = kk0 - above;
            }
        }
        __syncthreads();
    }

    const unsigned T  = s_prefix;
    const unsigned kk = s_k;

    int f[8], c = 0;
#pragma unroll
    for (int i = 0; i < 8; ++i) { f[i] = (act && v[i] == T) ? 1 : 0; c += f[i]; }
    int inc = c;
#pragma unroll
    for (int off = 1; off < 32; off <<= 1) {
        const int x = __shfl_up_sync(0xFFFFFFFFu, inc, off);
        if (lane >= off) inc += x;
    }
    if (lane == 31) warp_sums[wrp] = inc;
    __syncthreads();
    if (t == 0) {
        int run = 0;
#pragma unroll
        for (int w = 0; w < 8; ++w) { const int x = warp_sums[w]; warp_sums[w] = run; run += x; }
    }
    __syncthreads();
    int run = warp_sums[wrp] + (inc - c);   // exclusive tie count before roi 8t

    if (!act) return;
#pragma unroll
    for (int i = 0; i < 8; ++i) {
        const int n = t * 8 + i;
        const int gi = b * N_ROI + n;
        const bool pos = (v[i] > T) || (f[i] && (unsigned)run < kk);
        run += f[i];
        if (!pos) { g_label[gi] = -1; continue; }
        const int mi = g_maxidx[gi];
        const float4 q = roi[gi];
        const float4 g = gt[b * N_GT + mi];
        float bw = q.w - q.y;
        float bh = q.z - q.x;
        const float bcx = q.y + 0.5f * bw;
        const float bcy = q.x + 0.5f * bh;
        const float gw = g.w - g.y;
        const float gh = g.z - g.x;
        const float gcx = g.y + 0.5f * gw;
        const float gcy = g.x + 0.5f * gh;
        bw = (bw == 0.0f) ? 1e-3f : bw;
        bh = (bh == 0.0f) ? 1e-3f : bh;
        const float dx = (gw == 0.0f) ? 0.0f : (gcx - bcx) / bw;
        const float dy = (gh == 0.0f) ? 0.0f : (gcy - bcy) / bh;
        const float dw = (gw == 0.0f) ? 0.0f : logf(gw / bw);
        const float dh = (gh == 0.0f) ? 0.0f : logf(gh / bh);
        g_delta[gi] = make_float4(dy, dx, dh, dw);
        g_label[gi] = gtlab[b * N_GT + mi];
    }
}

// ---------------------------------------------------------------------------
// Writer tile: 1024 consecutive float4s of the fused output layout.
// ---------------------------------------------------------------------------
__device__ void write_tile(int tile, float4* __restrict__ out, int t)
{
    const int first = tile * WVEC;
    const int last  = (first + WVEC - 1 < ALL_VEC4 - 1) ? first + WVEC - 1
                                                        : ALL_VEC4 - 1;
    // Wait for the batches this tile touches (t == 0 spins, then block syncs).
    if (t == 0) {
        if (first < TOTAL_ROWS) {
            const int dl = (last < TOTAL_ROWS - 1) ? last : TOTAL_ROWS - 1;
            const int b1 = (first / N_LAB) / N_ROI;
            const int b2 = (dl    / N_LAB) / N_ROI;
            for (int bb = b1; bb <= b2; ++bb) waitb(bb);
        }
        if (last >= TOTAL_ROWS) {
            const int s  = (first > TOTAL_ROWS) ? first : TOTAL_ROWS;
            const int p1 = (s    - TOTAL_ROWS) * 4;
            const int p2 = (last - TOTAL_ROWS) * 4 + 3;
            const int b1 = (p1 / N_LAB) / N_ROI;
            int b2 = ((p2 / N_LAB) + 1) / N_ROI;   // +1: possible rr+1 access
            if (b2 > BATCH - 1) b2 = BATCH - 1;
            for (int bb = b1; bb <= b2; ++bb) waitb(bb);
        }
        __threadfence();
    }
    __syncthreads();

#pragma unroll
    for (int k = 0; k < WVEC / 256; ++k) {
        const int i = first + k * 256 + t;        // lanes contiguous -> coalesced
        if (i >= ALL_VEC4) break;
        if (i < TOTAL_ROWS) {
            const int fr = i / N_LAB;
            const int l  = i - fr * N_LAB;
            const int lab = g_label[fr];
            float4 dv = make_float4(0.f, 0.f, 0.f, 0.f);
            if (lab == l) dv = g_delta[fr];
            out[i] = dv;
        } else {
            const int j  = i - TOTAL_ROWS;
            const int p  = j * 4;
            const int rr = p / N_LAB;
            const int l0 = p - rr * N_LAB;
            const int labA = g_label[rr];
            const int eA = (labA < 0) ? 0 : labA;
            int eB = eA;
            if (l0 + 3 >= N_LAB) {
                const int labB = g_label[rr + 1];
                eB = (labB < 0) ? 0 : labB;
            }
            float w[4];
#pragma unroll
            for (int kk = 0; kk < 4; ++kk) {
                const int l = l0 + kk;
                const bool second = (l >= N_LAB);
                const int ll = second ? (l - N_LAB) : l;
                const int ee = second ? eB : eA;
                w[kk] = (ll == ee) ? 1.0f : 0.0f;
            }
            out[i] = make_float4(w[0], w[1], w[2], w[3]);
        }
    }
}

// ---------------------------------------------------------------------------
// Persistent single-wave kernel (1024 blocks; launch_bounds(256,8) guarantees
// 8 blocks/SM residency -> 1184 slots on 148 SMs >= 1024, so ALL blocks are
// co-resident and the flag-based grid sync cannot deadlock).
// Phase 1: iou chunk. Phase 2: last block of each batch -> select, set flag.
// Phase 3: every block writes its 1-2 output tiles, waiting only on the
// flags those tiles need. Last finishing block resets sync state.
// ---------------------------------------------------------------------------
__global__ void __launch_bounds__(256, 8)
fused_kernel(const float4* __restrict__ roi,
             const float4* __restrict__ gt,
             const int*    __restrict__ gtlab,
             float4*       __restrict__ out)
{
    const int bid = blockIdx.x;
    const int t   = threadIdx.x;

    // ---------------- Phase 1: iou ----------------
    const int b     = bid >> 5;
    const int chunk = bid & 31;

    __shared__ float4 sg[N_GT];
    __shared__ float  sga[N_GT];
    __shared__ int    s_last;

    if (t < N_GT) {
        const float4 g = gt[b * N_GT + t];
        sg[t]  = g;
        sga[t] = __fmul_rn(__fsub_rn(g.z, g.x), __fsub_rn(g.w, g.y));
    }
    __syncthreads();

    {
        const int local = t >> 2;
        const int seg   = t & 3;
        const int n     = chunk * RPB + local;
        const int nc    = (n < N_ROI) ? n : (N_ROI - 1);

        const float4 q = roi[b * N_ROI + nc];
        const float by1 = q.x, bx1 = q.y, by2 = q.z, bx2 = q.w;
        const float bb_area = __fmul_rn(__fsub_rn(by2, by1), __fsub_rn(bx2, bx1));

        const int m0 = seg * 25;
        float aI = 0.0f, aS = 1.0f; int ai = m0;
#pragma unroll
        for (int i = 0; i < 25; ++i) {
            const int m = m0 + i;
            const float4 g = sg[m];
            const float xt = fmaxf(bx1, g.y);
            const float yt = fmaxf(by1, g.x);
            const float xb = fminf(bx2, g.w);
            const float yb = fminf(by2, g.z);
            const float iw = fmaxf(__fsub_rn(xb, xt), 0.0f);
            const float ih = __fsub_rn(yb, yt);
            const float inter = __fmul_rn(iw, ih);
            const float S = __fadd_rn(bb_area, sga[m]);
            if (__fmul_rn(inter, aS) > __fmul_rn(aI, S)) { aI = inter; aS = S; ai = m; }
        }
#pragma unroll
        for (int off = 1; off < 4; off <<= 1) {
            const float oI = __shfl_xor_sync(0xFFFFFFFFu, aI, off);
            const float oS = __shfl_xor_sync(0xFFFFFFFFu, aS, off);
            const int   oi = __shfl_xor_sync(0xFFFFFFFFu, ai, off);
            const float x = __fmul_rn(oI, aS);
            const float y = __fmul_rn(aI, oS);
            if (x > y || (x == y && oi < ai)) { aI = oI; aS = oS; ai = oi; }
        }
        if (seg == 0 && n < N_ROI) {
            const float best = (aI > 0.0f) ? __fdividef(aI, __fsub_rn(aS, aI)) : 0.0f;
            g_merged[b * N_ROI + n] = __float_as_uint(best);
            g_maxidx[b * N_ROI + n] = ai;
        }
    }
    __threadfence();
    __syncthreads();

    // ---------------- Phase 2: select (last block of the batch) ----------------
    if (t == 0) s_last = (atomicAdd(&g_count[b], 1) == 31) ? 1 : 0;
    __syncthreads();
    if (s_last) {
        __threadfence();               // acquire the other 31 blocks' stores
        do_select(b, roi, gt, gtlab, t);
        __threadfence();               // release records
        __syncthreads();
        if (t == 0) atomicExch(&g_flag[b], 1);
    }

    // ---------------- Phase 3: write output tiles ----------------
    for (int tile = bid; tile < WTILES; tile += IBLK)
        write_tile(tile, out, t);

    // ---------------- Reset sync state for graph replay ----------------
    __syncthreads();
    if (t == 0) {
        if (atomicAdd(&g_wdone, 1) == IBLK - 1) {
#pragma unroll
            for (int bb = 0; bb < BATCH; ++bb) { g_count[bb] = 0; g_flag[bb] = 0; }
            g_wdone = 0;
        }
    }
}

// ---------------------------------------------------------------------------
extern "C" void kernel_launch(void* const* d_in, const int* in_sizes, int n_in,
                              void* d_out, int out_size)
{
    const float4* roi   = (const float4*)d_in[0];
    const float4* gt    = (const float4*)d_in[1];
    const int*    gtlab = (const int*)d_in[2];

    fused_kernel<<<IBLK, 256>>>(roi, gt, gtlab, (float4*)d_out);
}

// round 13
// speedup vs baseline: 1.1329x; 1.1329x over previous
#include <cuda_runtime.h>
#include <cuda_bf16.h>
#include <cstdint>

// Problem constants
#define BATCH 32
#define N_ROI 2000
#define N_GT  100
#define N_LAB 21
#define K_POS 64
#define ROWS_PER_B (N_ROI * N_LAB)            // 42000
#define DELTA_FLOATS (BATCH * ROWS_PER_B * 4) // 5,376,000
#define TOTAL_ROWS (BATCH * ROWS_PER_B)       // 1,344,000 (delta float4s; also label floats)
#define LAB_VEC4 (TOTAL_ROWS / 4)             // 336,000 label float4s
#define ALL_VEC4 (TOTAL_ROWS + LAB_VEC4)      // 1,680,000 fused float4 stores
#define RPB 64                                 // rois per iou block
#define IBLK 1024                              // 32 chunks x 32 batches

// Scratch (device globals; zero-initialized at module load; no runtime alloc)
__device__ unsigned int g_merged[BATCH * N_ROI];
__device__ int          g_maxidx[BATCH * N_ROI];
__device__ int          g_label [BATCH * N_ROI];   // gt label if positive, else -1
__device__ float4       g_delta [BATCH * N_ROI];   // valid only when positive
__device__ int          g_count [BATCH];           // iou blocks done per batch

// ---------------------------------------------------------------------------
// Select (256 threads; runs inside the LAST-arriving iou block of a batch —
// no waiting, no flags): exact stable-sort top-64 semantics via 4-pass radix
// select + index-ordered tie prefix, then per-roi label/delta records.
// Thread t owns rois [8t, 8t+8).
// ---------------------------------------------------------------------------
__device__ void do_select(int b, const float4* __restrict__ roi,
                          const float4* __restrict__ gt,
                          const int* __restrict__ gtlab, int t)
{
    __shared__ unsigned int hist[256];
    __shared__ unsigned int ssum[256];
    __shared__ unsigned int s_prefix, s_k;
    __shared__ int warp_sums[8];

    const int lane = t & 31, wrp = t >> 5;
    const bool act = (t < 250);                  // 250 * 8 = 2000
    const unsigned int* gm = g_merged + b * N_ROI;

    unsigned v[8];
#pragma unroll
    for (int i = 0; i < 8; ++i) v[i] = act ? gm[t * 8 + i] : 0u;
    if (t == 0) { s_prefix = 0u; s_k = K_POS; }
    __syncthreads();

#pragma unroll
    for (int pass = 0; pass < 4; ++pass) {
        const int shift = 24 - 8 * pass;
        hist[t] = 0u;
        __syncthreads();
        const unsigned pfx = s_prefix;
        const unsigned kk0 = s_k;
        const unsigned hm = (pass == 0) ? 0u
                          : (0xFFFFFFFFu << ((shift + 8 > 31) ? 31 : shift + 8));
#pragma unroll
        for (int i = 0; i < 8; ++i) {
            unsigned key = 0x100u, bin = 0u;
            if (act && (v[i] & hm) == (pfx & hm)) { bin = (v[i] >> shift) & 255u; key = bin; }
            const unsigned mmask = __match_any_sync(0xFFFFFFFFu, key);
            if (key != 0x100u && lane == (__ffs(mmask) - 1))
                atomicAdd(&hist[bin], (unsigned)__popc(mmask));
        }
        __syncthreads();
        if (t < 32) {       // single-warp suffix sum over 256 bins
            unsigned w[8], sum = 0u;
#pragma unroll
            for (int i = 0; i < 8; ++i) { w[i] = hist[t * 8 + i]; sum += w[i]; }
            unsigned suf = sum;
#pragma unroll
            for (int off = 1; off < 32; off <<= 1) {
                const unsigned x = __shfl_down_sync(0xFFFFFFFFu, suf, off);
                if (t + off < 32) suf += x;
            }
            unsigned acc = suf - sum;
#pragma unroll
            for (int i = 7; i >= 0; --i) { acc += w[i]; ssum[t * 8 + i] = acc; }
        }
        __syncthreads();
        {
            const unsigned cum   = ssum[t];
            const unsigned above = (t < 255) ? ssum[t + 1] : 0u;
            if (cum >= kk0 && above < kk0) {
                s_prefix = pfx | ((unsigned)t << shift);
                s_k = kk0 - above;
            }
        }
        __syncthreads();
    }

    const unsigned T  = s_prefix;
    const unsigned kk = s_k;

    int f[8], c = 0;
#pragma unroll
    for (int i = 0; i < 8; ++i) { f[i] = (act && v[i] == T) ? 1 : 0; c += f[i]; }
    int inc = c;
#pragma unroll
    for (int off = 1; off < 32; off <<= 1) {
        const int x = __shfl_up_sync(0xFFFFFFFFu, inc, off);
        if (lane >= off) inc += x;
    }
    if (lane == 31) warp_sums[wrp] = inc;
    __syncthreads();
    if (t == 0) {
        int run = 0;
#pragma unroll
        for (int w = 0; w < 8; ++w) { const int x = warp_sums[w]; warp_sums[w] = run; run += x; }
    }
    __syncthreads();
    int run = warp_sums[wrp] + (inc - c);   // exclusive tie count before roi 8t

    if (!act) return;
#pragma unroll
    for (int i = 0; i < 8; ++i) {
        const int n = t * 8 + i;
        const int gi = b * N_ROI + n;
        const bool pos = (v[i] > T) || (f[i] && (unsigned)run < kk);
        run += f[i];
        if (!pos) { g_label[gi] = -1; continue; }
        const int mi = g_maxidx[gi];
        const float4 q = roi[gi];
        const float4 g = gt[b * N_GT + mi];
        float bw = q.w - q.y;
        float bh = q.z - q.x;
        const float bcx = q.y + 0.5f * bw;
        const float bcy = q.x + 0.5f * bh;
        const float gw = g.w - g.y;
        const float gh = g.z - g.x;
        const float gcx = g.y + 0.5f * gw;
        const float gcy = g.x + 0.5f * gh;
        bw = (bw == 0.0f) ? 1e-3f : bw;
        bh = (bh == 0.0f) ? 1e-3f : bh;
        const float dx = (gw == 0.0f) ? 0.0f : (gcx - bcx) / bw;
        const float dy = (gh == 0.0f) ? 0.0f : (gcy - bcy) / bh;
        const float dw = (gw == 0.0f) ? 0.0f : logf(gw / bw);
        const float dh = (gh == 0.0f) ? 0.0f : logf(gh / bh);
        g_delta[gi] = make_float4(dy, dx, dh, dw);
        g_label[gi] = gtlab[b * N_GT + mi];
    }
}

// ---------------------------------------------------------------------------
// Kernel 1: iou (+ select in the last-arriving block of each batch).
// No inter-block waiting anywhere.
// ---------------------------------------------------------------------------
__global__ void __launch_bounds__(256)
iou_select_kernel(const float4* __restrict__ roi,
                  const float4* __restrict__ gt,
                  const int*    __restrict__ gtlab)
{
    const int bid   = blockIdx.x;
    const int t     = threadIdx.x;
    const int b     = bid >> 5;
    const int chunk = bid & 31;

    __shared__ float4 sg[N_GT];
    __shared__ float  sga[N_GT];
    __shared__ int    s_last;

    if (t < N_GT) {
        const float4 g = gt[b * N_GT + t];
        sg[t]  = g;
        sga[t] = __fmul_rn(__fsub_rn(g.z, g.x), __fsub_rn(g.w, g.y));
    }
    __syncthreads();

    {
        const int local = t >> 2;
        const int seg   = t & 3;
        const int n     = chunk * RPB + local;
        const int nc    = (n < N_ROI) ? n : (N_ROI - 1);

        const float4 q = roi[b * N_ROI + nc];
        const float by1 = q.x, bx1 = q.y, by2 = q.z, bx2 = q.w;
        const float bb_area = __fmul_rn(__fsub_rn(by2, by1), __fsub_rn(bx2, bx1));

        const int m0 = seg * 25;
        float aI = 0.0f, aS = 1.0f; int ai = m0;
#pragma unroll
        for (int i = 0; i < 25; ++i) {
            const int m = m0 + i;
            const float4 g = sg[m];
            const float xt = fmaxf(bx1, g.y);
            const float yt = fmaxf(by1, g.x);
            const float xb = fminf(bx2, g.w);
            const float yb = fminf(by2, g.z);
            const float iw = fmaxf(__fsub_rn(xb, xt), 0.0f);
            const float ih = __fsub_rn(yb, yt);
            const float inter = __fmul_rn(iw, ih);
            const float S = __fadd_rn(bb_area, sga[m]);
            if (__fmul_rn(inter, aS) > __fmul_rn(aI, S)) { aI = inter; aS = S; ai = m; }
        }
#pragma unroll
        for (int off = 1; off < 4; off <<= 1) {
            const float oI = __shfl_xor_sync(0xFFFFFFFFu, aI, off);
            const float oS = __shfl_xor_sync(0xFFFFFFFFu, aS, off);
            const int   oi = __shfl_xor_sync(0xFFFFFFFFu, ai, off);
            const float x = __fmul_rn(oI, aS);
            const float y = __fmul_rn(aI, oS);
            if (x > y || (x == y && oi < ai)) { aI = oI; aS = oS; ai = oi; }
        }
        if (seg == 0 && n < N_ROI) {
            const float best = (aI > 0.0f) ? __fdividef(aI, __fsub_rn(aS, aI)) : 0.0f;
            g_merged[b * N_ROI + n] = __float_as_uint(best);
            g_maxidx[b * N_ROI + n] = ai;
        }
    }
    __threadfence();
    __syncthreads();

    if (t == 0) s_last = (atomicAdd(&g_count[b], 1) == 31) ? 1 : 0;
    __syncthreads();
    if (s_last) {
        __threadfence();               // acquire the other 31 blocks' stores
        do_select(b, roi, gt, gtlab, t);
    }
}

// ---------------------------------------------------------------------------
// Kernel 2: fused output writer (one thread per output float4; 1.68M total).
// Block 0 also resets g_count for the next graph replay (kernel boundary
// guarantees all selects finished).
// ---------------------------------------------------------------------------
__global__ void __launch_bounds__(256) write_kernel(float4* __restrict__ out)
{
    const int i = blockIdx.x * 256 + threadIdx.x;
    if (blockIdx.x == 0 && threadIdx.x < BATCH) g_count[threadIdx.x] = 0;
    if (i >= ALL_VEC4) return;

    if (i < TOTAL_ROWS) {
        // Delta row: flat row index i = flatroi*21 + l
        const int fr = i / N_LAB;             // flat roi index (b*N_ROI + n)
        const int l  = i - fr * N_LAB;
        const int lab = g_label[fr];
        float4 dv = make_float4(0.f, 0.f, 0.f, 0.f);
        if (lab == l) dv = g_delta[fr];
        out[i] = dv;
    } else {
        const int j  = i - TOTAL_ROWS;        // label float4 index
        const int p  = j * 4;                 // flat label element index
        const int rr = p / N_LAB;             // flat roi index
        const int l0 = p - rr * N_LAB;

        const int labA = g_label[rr];
        const int eA = (labA < 0) ? 0 : labA;
        int eB = eA;
        if (l0 + 3 >= N_LAB) {                // crosses into next roi
            const int labB = g_label[rr + 1];
            eB = (labB < 0) ? 0 : labB;
        }

        float v[4];
#pragma unroll
        for (int k = 0; k < 4; ++k) {
            const int l = l0 + k;
            const bool second = (l >= N_LAB);
            const int ll = second ? (l - N_LAB) : l;
            const int ee = second ? eB : eA;
            v[k] = (ll == ee) ? 1.0f : 0.0f;
        }
        out[i] = make_float4(v[0], v[1], v[2], v[3]);
    }
}

// ---------------------------------------------------------------------------
extern "C" void kernel_launch(void* const* d_in, const int* in_sizes, int n_in,
                              void* d_out, int out_size)
{
    const float4* roi   = (const float4*)d_in[0];
    const float4* gt    = (const float4*)d_in[1];
    const int*    gtlab = (const int*)d_in[2];

    iou_select_kernel<<<IBLK, 256>>>(roi, gt, gtlab);
    write_kernel<<<(ALL_VEC4 + 255) / 256, 256>>>((float4*)d_out);
}

// round 14
// speedup vs baseline: 1.5407x; 1.3600x over previous
#include <cuda_runtime.h>
#include <cuda_bf16.h>
#include <cstdint>

// Problem constants
#define BATCH 32
#define N_ROI 2000
#define N_GT  100
#define N_LAB 21
#define K_POS 64
#define ROWS_PER_B (N_ROI * N_LAB)            // 42000
#define DELTA_FLOATS (BATCH * ROWS_PER_B * 4) // 5,376,000
#define TOTAL_ROWS (BATCH * ROWS_PER_B)       // 1,344,000 (delta float4s; also label floats)
#define LAB_VEC4 (TOTAL_ROWS / 4)             // 336,000 label float4s
#define NROIS_ALL (BATCH * N_ROI)             // 64,000
#define RPB 64                                 // rois per iou block

// Writer tiling
#define D_RPB 48                               // rois per delta-writer block
#define D_V4  (D_RPB * N_LAB)                  // 1008 float4s per delta block
#define DBLK  ((NROIS_ALL + D_RPB - 1) / D_RPB)  // 1334
#define L_RPB 64                               // rois per label-writer block
#define L_V4  (L_RPB * N_LAB / 4)              // 336 float4s per label block
#define LBLK  (NROIS_ALL / L_RPB)              // 1000 (64000 % 64 == 0)
#define WBLK  (DBLK + LBLK)

// Scratch (device globals; no runtime allocation)
__device__ unsigned int g_merged[BATCH * N_ROI];
__device__ int          g_maxidx[BATCH * N_ROI];
__device__ int          g_label [BATCH * N_ROI];   // gt label if positive, else -1
__device__ float4       g_delta [BATCH * N_ROI];   // valid only when positive

// ---------------------------------------------------------------------------
// Kernel A: per-roi max IoU + first-argmax over 100 gt boxes (round-9 shape).
// IoU = inter/(S - inter), S = bb_area + gt_area: increasing in inter/S, so
// the in-loop union subtraction disappears; cross-multiplied compare (S > 0).
// Zero-overlap ties exact: 0 > 0 false -> first index wins.
// ---------------------------------------------------------------------------
__global__ void __launch_bounds__(256) iou_kernel(const float4* __restrict__ roi,
                                                  const float4* __restrict__ gt)
{
    __shared__ float4 sg[N_GT];
    __shared__ float  sga[N_GT];
    const int b = blockIdx.y;
    const int t = threadIdx.x;

    if (t < N_GT) {
        const float4 g = gt[b * N_GT + t];
        sg[t]  = g;
        sga[t] = __fmul_rn(__fsub_rn(g.z, g.x), __fsub_rn(g.w, g.y));
    }
    __syncthreads();

    const int local = t >> 2;                 // 0..63 : roi within block
    const int seg   = t & 3;                  // 0..3  : gt segment
    const int n     = blockIdx.x * RPB + local;
    const int nc    = (n < N_ROI) ? n : (N_ROI - 1);   // clamp: no guard in loop

    const float4 q = roi[b * N_ROI + nc];
    const float by1 = q.x, bx1 = q.y, by2 = q.z, bx2 = q.w;
    const float bb_area = __fmul_rn(__fsub_rn(by2, by1), __fsub_rn(bx2, bx1));

    const int m0 = seg * 25;
    float aI = 0.0f, aS = 1.0f; int ai = m0;

#pragma unroll
    for (int i = 0; i < 25; ++i) {
        const int m = m0 + i;
        const float4 g = sg[m];
        const float xt = fmaxf(bx1, g.y);
        const float yt = fmaxf(by1, g.x);
        const float xb = fminf(bx2, g.w);
        const float yb = fminf(by2, g.z);
        const float iw = fmaxf(__fsub_rn(xb, xt), 0.0f);
        const float ih = __fsub_rn(yb, yt);
        const float inter = __fmul_rn(iw, ih);
        const float S = __fadd_rn(bb_area, sga[m]);
        if (__fmul_rn(inter, aS) > __fmul_rn(aI, S)) { aI = inter; aS = S; ai = m; }
    }

#pragma unroll
    for (int off = 1; off < 4; off <<= 1) {
        const float oI = __shfl_xor_sync(0xFFFFFFFFu, aI, off);
        const float oS = __shfl_xor_sync(0xFFFFFFFFu, aS, off);
        const int   oi = __shfl_xor_sync(0xFFFFFFFFu, ai, off);
        const float x = __fmul_rn(oI, aS);
        const float y = __fmul_rn(aI, oS);
        if (x > y || (x == y && oi < ai)) { aI = oI; aS = oS; ai = oi; }
    }

    if (seg == 0 && n < N_ROI) {
        const float best = (aI > 0.0f) ? __fdividef(aI, __fsub_rn(aS, aI)) : 0.0f;
        g_merged[b * N_ROI + n] = __float_as_uint(best);
        g_maxidx[b * N_ROI + n] = ai;
    }
}

// ---------------------------------------------------------------------------
// Kernel B: per-batch top-64 selection (exact stable-sort semantics) and
// per-roi label/delta records. One block per batch, 1024 threads, 2 rois/thr.
// ---------------------------------------------------------------------------
__global__ void __launch_bounds__(1024) select_kernel(const float4* __restrict__ roi,
                                                      const float4* __restrict__ gt,
                                                      const int*    __restrict__ gtlab)
{
    __shared__ unsigned int hist[256];
    __shared__ unsigned int ssum[256];
    __shared__ unsigned int s_prefix, s_k;
    __shared__ int warp_sums[32];

    const int b = blockIdx.x;
    const int t = threadIdx.x;
    const int n0 = 2 * t, n1 = 2 * t + 1;
    const bool act = (n0 < N_ROI);
    const int lane = t & 31, wid = t >> 5;

    const unsigned int* gm = g_merged + b * N_ROI;
    unsigned v0 = 0u, v1 = 0u;
    if (act) { v0 = gm[n0]; v1 = gm[n1]; }
    if (t == 0) { s_prefix = 0u; s_k = K_POS; }
    __syncthreads();

#pragma unroll
    for (int pass = 0; pass < 4; ++pass) {
        const int shift = 24 - 8 * pass;
        if (t < 256) hist[t] = 0u;
        __syncthreads();
        const unsigned pfx = s_prefix;
        const unsigned kk0 = s_k;
        const unsigned hm = (pass == 0) ? 0u
                          : (0xFFFFFFFFu << ((shift + 8 > 31) ? 31 : shift + 8));
#pragma unroll
        for (int s = 0; s < 2; ++s) {
            const unsigned v = (s == 0) ? v0 : v1;
            unsigned key = 0x100u, bin = 0u;
            if (act && (v & hm) == (pfx & hm)) { bin = (v >> shift) & 255u; key = bin; }
            const unsigned mmask = __match_any_sync(0xFFFFFFFFu, key);
            if (key != 0x100u && lane == (__ffs(mmask) - 1))
                atomicAdd(&hist[bin], (unsigned)__popc(mmask));
        }
        __syncthreads();
        if (t < 32) {
            unsigned v[8], sum = 0u;
#pragma unroll
            for (int i = 0; i < 8; ++i) { v[i] = hist[t * 8 + i]; sum += v[i]; }
            unsigned suf = sum;
#pragma unroll
            for (int off = 1; off < 32; off <<= 1) {
                const unsigned x = __shfl_down_sync(0xFFFFFFFFu, suf, off);
                if (t + off < 32) suf += x;
            }
            unsigned acc = suf - sum;
#pragma unroll
            for (int i = 7; i >= 0; --i) { acc += v[i]; ssum[t * 8 + i] = acc; }
        }
        __syncthreads();
        if (t < 256) {
            const unsigned cum   = ssum[t];
            const unsigned above = (t < 255) ? ssum[t + 1] : 0u;
            if (cum >= kk0 && above < kk0) {
                s_prefix = pfx | ((unsigned)t << shift);
                s_k = kk0 - above;
            }
        }
        __syncthreads();
    }

    const unsigned T  = s_prefix;
    const unsigned kk = s_k;

    const int f0 = (act && v0 == T) ? 1 : 0;
    const int f1 = (act && v1 == T) ? 1 : 0;
    const int c  = f0 + f1;
    int inc = c;
#pragma unroll
    for (int off = 1; off < 32; off <<= 1) {
        const int x = __shfl_up_sync(0xFFFFFFFFu, inc, off);
        if (lane >= off) inc += x;
    }
    if (lane == 31) warp_sums[wid] = inc;
    __syncthreads();
    if (t < 32) {
        const int v = warp_sums[t];
        int iv = v;
#pragma unroll
        for (int off = 1; off < 32; off <<= 1) {
            const int x = __shfl_up_sync(0xFFFFFFFFu, iv, off);
            if (t >= off) iv += x;
        }
        warp_sums[t] = iv - v;
    }
    __syncthreads();
    const int excl = warp_sums[wid] + (inc - c);

    if (!act) return;

    const bool pos0 = (v0 > T) || (f0 && (unsigned)excl        < kk);
    const bool pos1 = (v1 > T) || (f1 && (unsigned)(excl + f0) < kk);

#pragma unroll
    for (int s = 0; s < 2; ++s) {
        const int n = (s == 0) ? n0 : n1;
        const bool pos = (s == 0) ? pos0 : pos1;
        const int gi = b * N_ROI + n;
        if (!pos) { g_label[gi] = -1; continue; }
        const int mi = g_maxidx[gi];
        const float4 q = roi[gi];
        const float4 g = gt[b * N_GT + mi];
        float bw = q.w - q.y;
        float bh = q.z - q.x;
        const float bcx = q.y + 0.5f * bw;
        const float bcy = q.x + 0.5f * bh;
        const float gw = g.w - g.y;
        const float gh = g.z - g.x;
        const float gcx = g.y + 0.5f * gw;
        const float gcy = g.x + 0.5f * gh;
        bw = (bw == 0.0f) ? 1e-3f : bw;
        bh = (bh == 0.0f) ? 1e-3f : bh;
        const float dx = (gw == 0.0f) ? 0.0f : (gcx - bcx) / bw;
        const float dy = (gh == 0.0f) ? 0.0f : (gcy - bcy) / bh;
        const float dw = (gw == 0.0f) ? 0.0f : logf(gw / bw);
        const float dh = (gh == 0.0f) ? 0.0f : logf(gh / bh);
        g_delta[gi] = make_float4(dy, dx, dh, dw);
        g_label[gi] = gtlab[b * N_GT + mi];
    }
}

// ---------------------------------------------------------------------------
// Kernel C: staged writer. Two roles by blockIdx.x:
//  [0, DBLK)        delta role: 48 rois/block -> stage 48 labels + 48 deltas
//                   in smem, then 1008 contiguous float4 stores fed from LDS.
//  [DBLK, WBLK)     label role: 64 rois/block = exactly 336 label float4s
//                   (64*21 divisible by 4) -> stage 64 labels, stream stores.
// No per-store-thread dependent global loads anywhere.
// ---------------------------------------------------------------------------
__global__ void __launch_bounds__(256) write_kernel(float4* __restrict__ out)
{
    const int t = threadIdx.x;

    if (blockIdx.x < DBLK) {
        // ---- delta role ----
        __shared__ int    s_lab[D_RPB];
        __shared__ float4 s_del[D_RPB];
        const int fr0 = blockIdx.x * D_RPB;
        const int cnt = (fr0 + D_RPB <= NROIS_ALL) ? D_RPB : (NROIS_ALL - fr0);

        if (t < cnt) {
            s_lab[t] = g_label[fr0 + t];
            s_del[t] = g_delta[fr0 + t];
        }
        __syncthreads();

        const int nv = cnt * N_LAB;           // float4s this block writes
        float4* dst = out + (size_t)fr0 * N_LAB;
#pragma unroll
        for (int k = 0; k < (D_V4 + 255) / 256; ++k) {
            const int j = k * 256 + t;
            if (j < nv) {
                const int fr = j / N_LAB;     // 0..47 (const-div -> mulhi)
                const int l  = j - fr * N_LAB;
                const int lab = s_lab[fr];
                float4 dv = make_float4(0.f, 0.f, 0.f, 0.f);
                if (lab == l) dv = s_del[fr];
                dst[j] = dv;
            }
        }
    } else {
        // ---- label role ----
        __shared__ int s_e[L_RPB];
        const int e   = blockIdx.x - DBLK;
        const int fr0 = e * L_RPB;

        if (t < L_RPB) {
            const int lab = g_label[fr0 + t];
            s_e[t] = (lab < 0) ? 0 : lab;
        }
        __syncthreads();

        float4* dst = out + TOTAL_ROWS + (size_t)e * L_V4;
#pragma unroll
        for (int k = 0; k < (L_V4 + 255) / 256; ++k) {
            const int j = k * 256 + t;
            if (j < L_V4) {
                const int p  = j * 4;                 // label element index (block-local)
                const int r0 = p / N_LAB;             // 0..63
                const int l0 = p - r0 * N_LAB;
                const int e0 = s_e[r0];
                const int e1 = s_e[(r0 + 1 < L_RPB) ? r0 + 1 : r0];
                float v[4];
#pragma unroll
                for (int kk = 0; kk < 4; ++kk) {
                    const int l = l0 + kk;
                    const bool second = (l >= N_LAB);
                    const int ll = second ? (l - N_LAB) : l;
                    const int ee = second ? e1 : e0;
                    v[kk] = (ll == ee) ? 1.0f : 0.0f;
                }
                dst[j] = make_float4(v[0], v[1], v[2], v[3]);
            }
        }
    }
}

// ---------------------------------------------------------------------------
extern "C" void kernel_launch(void* const* d_in, const int* in_sizes, int n_in,
                              void* d_out, int out_size)
{
    const float4* roi   = (const float4*)d_in[0];
    const float4* gt    = (const float4*)d_in[1];
    const int*    gtlab = (const int*)d_in[2];

    dim3 gA((N_ROI + RPB - 1) / RPB, BATCH);
    iou_kernel<<<gA, 256>>>(roi, gt);
    select_kernel<<<BATCH, 1024>>>(roi, gt, gtlab);
    write_kernel<<<WBLK, 256>>>((float4*)d_out);
}